// round 15
// baseline (speedup 1.0000x reference)
#include <cuda_runtime.h>
#include <cuda_bf16.h>
#include <cstdint>

typedef unsigned long long ull;

#define M_TOT 16384   // B * L
#define L_SEQ 4096
#define NCHUNK 64
#define CLEN 64
#define LOG2E 1.4426950408889634f
#define SPITCH 68     // scan smem row pitch (floats): 16B-aligned, conflict-free

// ---------------- scratch ----------------------------------------------------
__device__ __align__(16) float g_xz[1024 * M_TOT];    // in_proj out (n,m), n<512 used (xs_pre)
__device__ __align__(16) float g_xdbl[M_TOT * 48];    // x_proj out, (m, j)
__device__ __align__(16) float g_delta[512 * M_TOT];  // softplus, (d, m)
__device__ __align__(16) float g_P[NCHUNK * 2048 * 16];
__device__ __align__(16) float g_Lh[NCHUNK * 2048 * 16];
__device__ __align__(16) float g_H[NCHUNK * 2048 * 16];
__device__ __align__(16) __nv_bfloat16 g_xsH[512 * M_TOT];  // conv+silu hi, (d,m)
__device__ __align__(16) __nv_bfloat16 g_xsL[512 * M_TOT];  // conv+silu lo
__device__ __align__(16) __nv_bfloat16 g_zsH[512 * M_TOT];  // raw z hi, (d,m)
__device__ __align__(16) __nv_bfloat16 g_zsL[512 * M_TOT];  // raw z lo
__device__ __align__(16) __nv_bfloat16 g_XnH[256 * M_TOT];
__device__ __align__(16) __nv_bfloat16 g_XnL[256 * M_TOT];
__device__ __align__(16) __nv_bfloat16 g_yH[512 * M_TOT];
__device__ __align__(16) __nv_bfloat16 g_yL[512 * M_TOT];
__device__ __align__(16) __nv_bfloat16 g_WtH[1024 * 256];
__device__ __align__(16) __nv_bfloat16 g_WtL[1024 * 256];
__device__ __align__(16) __nv_bfloat16 g_WcH[128 * 512];
__device__ __align__(16) __nv_bfloat16 g_WcL[128 * 512];

// ---------------- helpers ----------------------------------------------------
__device__ __forceinline__ uint32_t smem_u32(const void* p) {
    uint32_t a;
    asm("{ .reg .u64 t; cvta.to.shared.u64 t, %1; cvt.u32.u64 %0, t; }" : "=r"(a) : "l"(p));
    return a;
}
__device__ __forceinline__ float ex2(float x) {
    float r;
    asm("ex2.approx.f32 %0, %1;" : "=f"(r) : "f"(x));
    return r;
}
__device__ __forceinline__ void ldsm4(uint32_t* r, uint32_t addr) {
    asm volatile("ldmatrix.sync.aligned.m8n8.x4.shared.b16 {%0,%1,%2,%3}, [%4];"
        : "=r"(r[0]), "=r"(r[1]), "=r"(r[2]), "=r"(r[3]) : "r"(addr));
}
__device__ __forceinline__ void ldsm4t(uint32_t* r, uint32_t addr) {
    asm volatile("ldmatrix.sync.aligned.m8n8.x4.trans.shared.b16 {%0,%1,%2,%3}, [%4];"
        : "=r"(r[0]), "=r"(r[1]), "=r"(r[2]), "=r"(r[3]) : "r"(addr));
}
__device__ __forceinline__ void mma_bf16(float* d, const uint32_t* a, const uint32_t* b) {
    asm volatile("mma.sync.aligned.m16n8k16.row.col.f32.bf16.bf16.f32 "
        "{%0,%1,%2,%3}, {%4,%5,%6,%7}, {%8,%9}, {%0,%1,%2,%3};"
        : "+f"(d[0]), "+f"(d[1]), "+f"(d[2]), "+f"(d[3])
        : "r"(a[0]), "r"(a[1]), "r"(a[2]), "r"(a[3]), "r"(b[0]), "r"(b[1]));
}
// load 4 floats reconstructed from bf16 hi/lo arrays (idx 4-elem aligned)
__device__ __forceinline__ float4 ld_hl4(const __nv_bfloat16* __restrict__ H,
                                         const __nv_bfloat16* __restrict__ L, size_t idx) {
    uint2 uh = *(const uint2*)(H + idx);
    uint2 ul = *(const uint2*)(L + idx);
    __nv_bfloat162 a, b, c, d;
    *(uint32_t*)&a = uh.x; *(uint32_t*)&b = uh.y;
    *(uint32_t*)&c = ul.x; *(uint32_t*)&d = ul.y;
    float2 fa = __bfloat1622float2(a), fb = __bfloat1622float2(b);
    float2 fc = __bfloat1622float2(c), fd = __bfloat1622float2(d);
    return make_float4(fa.x + fc.x, fa.y + fc.y, fb.x + fd.x, fb.y + fd.y);
}
// store 2 floats split hi/lo (idx 2-elem aligned)
__device__ __forceinline__ void st_hl2(__nv_bfloat16* __restrict__ H,
                                       __nv_bfloat16* __restrict__ L,
                                       size_t idx, float2 v) {
    __nv_bfloat16 h0 = __float2bfloat16(v.x), h1 = __float2bfloat16(v.y);
    __nv_bfloat16 l0 = __float2bfloat16(v.x - __bfloat162float(h0));
    __nv_bfloat16 l1 = __float2bfloat16(v.y - __bfloat162float(h1));
    __nv_bfloat162 hh; hh.x = h0; hh.y = h1;
    __nv_bfloat162 ll; ll.x = l0; ll.y = l1;
    *(__nv_bfloat162*)(H + idx) = hh;
    *(__nv_bfloat162*)(L + idx) = ll;
}
#define CPA16(dst, src) asm volatile("cp.async.cg.shared.global [%0], [%1], 16;" :: "r"(dst), "l"(src))
#define CPA_COMMIT()    asm volatile("cp.async.commit_group;" ::: "memory")
#define CPA_WAIT(n)     asm volatile("cp.async.wait_group %0;" :: "n"(n) : "memory")

// ---------------- K_wt: split-transpose in_proj_w -> [n][k] bf16 ------------
__global__ void k_wt(const float* __restrict__ W) {
    __shared__ float t[32][33];
    int n0 = blockIdx.x * 32, k0 = blockIdx.y * 32;
    int x = threadIdx.x, y0 = threadIdx.y;
    for (int yy = y0; yy < 32; yy += 8) t[yy][x] = W[(k0 + yy) * 1024 + n0 + x];
    __syncthreads();
    for (int yy = y0; yy < 32; yy += 8) {
        float v = t[x][yy];
        __nv_bfloat16 h = __float2bfloat16(v);
        __nv_bfloat16 l = __float2bfloat16(v - __bfloat162float(h));
        g_WtH[(size_t)(n0 + yy) * 256 + k0 + x] = h;
        g_WtL[(size_t)(n0 + yy) * 256 + k0 + x] = l;
    }
}

// ---------------- K_wc: (mow @ outp_w)^T split ------------------------------
__global__ void k_wc(const float* __restrict__ mw, const float* __restrict__ ow) {
    int d = blockIdx.x, e = threadIdx.x;
    float acc = 0.f;
#pragma unroll 8
    for (int c = 0; c < 256; ++c)
        acc = fmaf(mw[d * 256 + c], ow[c * 128 + e], acc);
    __nv_bfloat16 h = __float2bfloat16(acc);
    __nv_bfloat16 l = __float2bfloat16(acc - __bfloat162float(h));
    g_WcH[(size_t)e * 512 + d] = h;
    g_WcL[(size_t)e * 512 + d] = l;
}

// ---------------- K1: concat + LN, 4 threads per token ----------------------
__global__ void __launch_bounds__(256) k_ln(const float* __restrict__ in1,
                                            const float* __restrict__ in2,
                                            const float* __restrict__ gg,
                                            const float* __restrict__ bb) {
    __shared__ float sg[256], sb[256];
    __shared__ float red[2][4][64];
    int tid = threadIdx.x;
    int q = tid >> 6, ml = tid & 63;
    sg[tid] = gg[tid]; sb[tid] = bb[tid];

    int m = blockIdx.x * 64 + ml;
    int b = m >> 12, t = m & 4095;
    const float* src = ((q < 2) ? in1 : in2) + (size_t)b * 128 * 4096 + t;
    int c0 = (q & 1) * 64;

    float vals[64];
    float s = 0.f, s2 = 0.f;
#pragma unroll
    for (int i = 0; i < 64; ++i) {
        float v = src[(size_t)(c0 + i) * 4096];
        vals[i] = v; s += v; s2 += v * v;
    }
    red[0][q][ml] = s; red[1][q][ml] = s2;
    __syncthreads();
    s  = red[0][0][ml] + red[0][1][ml] + red[0][2][ml] + red[0][3][ml];
    s2 = red[1][0][ml] + red[1][1][ml] + red[1][2][ml] + red[1][3][ml];
    float mu = s * (1.f / 256.f);
    float var = s2 * (1.f / 256.f) - mu * mu;
    float rs = rsqrtf(var + 1e-5f);

    int cbase = q * 64;
#pragma unroll
    for (int i = 0; i < 64; ++i) {
        int c = cbase + i;
        float o = (vals[i] - mu) * rs * sg[c] + sb[c];
        __nv_bfloat16 h = __float2bfloat16(o);
        __nv_bfloat16 l = __float2bfloat16(o - __bfloat162float(h));
        g_XnH[(size_t)c * M_TOT + m] = h;
        g_XnL[(size_t)c * M_TOT + m] = l;
    }
}

// ---------------- warp-MMA GEMM: split bf16, cp.async 3-stage ----------------
// in_proj epilogue: n<512 -> fp32 g_xz (conv input); n>=512 -> raw z bf16 H/L.
#define STG_SZ 65536
#define SMEM_MMA 196608

template<int KT, bool IS_OUT>
__global__ void __launch_bounds__(256) k_mma(
    const __nv_bfloat16* __restrict__ AH, const __nv_bfloat16* __restrict__ AL,
    const __nv_bfloat16* __restrict__ BH, const __nv_bfloat16* __restrict__ BL,
    float* __restrict__ outp, const float* __restrict__ bias)
{
    extern __shared__ __align__(16) char sm[];
    const int tid = threadIdx.x;
    const int lane = tid & 31, wid = tid >> 5;
    const int wr = wid & 1, wc = wid >> 1;
    const int m0 = blockIdx.x * 128, n0 = blockIdx.y * 128;
    const uint32_t smb = smem_u32(sm);
    const int NK = KT / 64;

    float acc[4][4][4];
#pragma unroll
    for (int i = 0; i < 4; ++i)
#pragma unroll
        for (int j = 0; j < 4; ++j)
#pragma unroll
            for (int p = 0; p < 4; ++p) acc[i][j][p] = 0.f;

    auto stage = [&](int kc, int stg) {
        uint32_t base = smb + stg * STG_SZ;
#pragma unroll
        for (int it = 0; it < 4; ++it) {
            int cid = it * 256 + tid;
            int row = cid >> 3, seg = cid & 7;
            size_t gof = (size_t)(n0 + row) * KT + kc * 64 + seg * 8;
            uint32_t off = row * 128 + ((seg ^ (row & 7)) << 4);
            CPA16(base + off, AH + gof);
            CPA16(base + 16384 + off, AL + gof);
        }
#pragma unroll
        for (int it = 0; it < 4; ++it) {
            int cid = it * 256 + tid;
            int k = cid >> 4, mseg = cid & 15;
            size_t gof = (size_t)(kc * 64 + k) * M_TOT + m0 + mseg * 8;
            uint32_t off = k * 256 + ((mseg ^ (k & 7)) << 4);
            CPA16(base + 32768 + off, BH + gof);
            CPA16(base + 49152 + off, BL + gof);
        }
    };

    stage(0, 0); CPA_COMMIT();
    if (NK > 1) { stage(1, 1); CPA_COMMIT(); }

    for (int kc = 0; kc < NK; ++kc) {
        if (kc + 1 < NK) CPA_WAIT(1); else CPA_WAIT(0);
        __syncthreads();
        if (kc + 2 < NK) { stage(kc + 2, (kc + 2) % 3); CPA_COMMIT(); }

        uint32_t sa_h = smb + (kc % 3) * STG_SZ;
        uint32_t sa_l = sa_h + 16384;
        uint32_t sb_h = sa_h + 32768;
        uint32_t sb_l = sa_h + 49152;

#pragma unroll
        for (int ks = 0; ks < 4; ++ks) {
            uint32_t afh[4][4], afl[4][4];
            {
                int row = wr * 64 + (lane & 7) + ((lane >> 3) & 1) * 8;
                int seg = ks * 2 + (lane >> 4);
#pragma unroll
                for (int rt = 0; rt < 4; ++rt) {
                    int r = row + rt * 16;
                    uint32_t off = r * 128 + ((seg ^ (r & 7)) << 4);
                    ldsm4(afh[rt], sa_h + off);
                    ldsm4(afl[rt], sa_l + off);
                }
            }
            uint32_t bfh[4][2], bfl[4][2];
            {
                int k = ks * 16 + (lane & 7) + ((lane >> 3) & 1) * 8;
#pragma unroll
                for (int half = 0; half < 2; ++half) {
                    int mseg = wc * 4 + half * 2 + (lane >> 4);
                    uint32_t off = k * 256 + ((mseg ^ (k & 7)) << 4);
                    uint32_t r[4];
                    ldsm4t(r, sb_h + off);
                    bfh[half * 2][0] = r[0]; bfh[half * 2][1] = r[1];
                    bfh[half * 2 + 1][0] = r[2]; bfh[half * 2 + 1][1] = r[3];
                    ldsm4t(r, sb_l + off);
                    bfl[half * 2][0] = r[0]; bfl[half * 2][1] = r[1];
                    bfl[half * 2 + 1][0] = r[2]; bfl[half * 2 + 1][1] = r[3];
                }
            }
#pragma unroll
            for (int rt = 0; rt < 4; ++rt)
#pragma unroll
                for (int ct = 0; ct < 4; ++ct) {
                    mma_bf16(acc[rt][ct], afh[rt], bfh[ct]);
                    mma_bf16(acc[rt][ct], afh[rt], bfl[ct]);
                    mma_bf16(acc[rt][ct], afl[rt], bfh[ct]);
                }
        }
    }

    const bool ZPART = (!IS_OUT) && (n0 >= 512);
#pragma unroll
    for (int rt = 0; rt < 4; ++rt) {
        int row0 = n0 + wr * 64 + rt * 16 + (lane >> 2);
        int row1 = row0 + 8;
        float b0 = 0.f, b1 = 0.f;
        if (IS_OUT) { b0 = bias[row0]; b1 = bias[row1]; }
#pragma unroll
        for (int ct = 0; ct < 4; ++ct) {
            int col = m0 + wc * 32 + ct * 8 + (lane & 3) * 2;
            float2 v0 = make_float2(acc[rt][ct][0] + b0, acc[rt][ct][1] + b0);
            float2 v1 = make_float2(acc[rt][ct][2] + b1, acc[rt][ct][3] + b1);
            if (IS_OUT) {
                int bb = col >> 12, t = col & 4095;
                *(float2*)&outp[((size_t)(bb * 128 + row0) << 12) + t] = v0;
                *(float2*)&outp[((size_t)(bb * 128 + row1) << 12) + t] = v1;
            } else if (ZPART) {
                st_hl2(g_zsH, g_zsL, (size_t)(row0 - 512) * M_TOT + col, v0);
                st_hl2(g_zsH, g_zsL, (size_t)(row1 - 512) * M_TOT + col, v1);
            } else {
                *(float2*)&outp[(size_t)row0 * M_TOT + col] = v0;
                *(float2*)&outp[(size_t)row1 * M_TOT + col] = v1;
            }
        }
    }
}

// ---------------- K3: causal dwconv(4) + bias + silu -> bf16 H/L ------------
__global__ void k_conv(const float* __restrict__ cw, const float* __restrict__ cb) {
    int d = blockIdx.y;
    int m4 = (blockIdx.x * 256 + threadIdx.x) * 4;
    int t4 = m4 & 4095;
    const float* row = g_xz + (size_t)d * M_TOT;
    float4 v = *(const float4*)&row[m4];
    float4 vp = (t4 == 0) ? make_float4(0.f, 0.f, 0.f, 0.f)
                          : *(const float4*)&row[m4 - 4];
    float w0 = cw[d * 4 + 0], w1 = cw[d * 4 + 1], w2 = cw[d * 4 + 2], w3 = cw[d * 4 + 3];
    float bia = cb[d];
    float4 o;
    o.x = bia + w3 * v.x + w2 * vp.w + w1 * vp.z + w0 * vp.y;
    o.y = bia + w3 * v.y + w2 * v.x + w1 * vp.w + w0 * vp.z;
    o.z = bia + w3 * v.z + w2 * v.y + w1 * v.x + w0 * vp.w;
    o.w = bia + w3 * v.w + w2 * v.z + w1 * v.y + w0 * v.x;
    o.x = o.x / (1.f + __expf(-o.x));
    o.y = o.y / (1.f + __expf(-o.y));
    o.z = o.z / (1.f + __expf(-o.z));
    o.w = o.w / (1.f + __expf(-o.w));
    size_t idx = (size_t)d * M_TOT + m4;
    st_hl2(g_xsH, g_xsL, idx, make_float2(o.x, o.y));
    st_hl2(g_xsH, g_xsL, idx + 2, make_float2(o.z, o.w));
}

// ---------------- K4: x_proj + dt_proj fused, m-tile 64, grid 256 -----------
__global__ void __launch_bounds__(256) k_xproj(const float* __restrict__ xw,
                                               const float* __restrict__ dtw,
                                               const float* __restrict__ db) {
    __shared__ __align__(16) float Ash[32][64];
    __shared__ float Wsh[32][48];
    __shared__ float sdt[64][17];
    __shared__ float shw[16][128];
    __shared__ float shb[128];
    int tid = threadIdx.x;
    int m0 = blockIdx.x * 64;
    int tj = tid >> 5, tm = tid & 31;
    float acc[6][2] = {};

    for (int k0 = 0; k0 < 512; k0 += 32) {
#pragma unroll
        for (int r = 0; r < 2; ++r) {
            int lin = r * 256 + tid;
            int row = lin >> 4, c4 = (lin & 15) << 2;
            float4 f = ld_hl4(g_xsH, g_xsL, (size_t)(k0 + row) * M_TOT + m0 + c4);
            *(float4*)&Ash[row][c4] = f;
        }
#pragma unroll
        for (int r = 0; r < 6; ++r) {
            int lin = r * 256 + tid;
            int row = lin / 48, col = lin % 48;
            Wsh[row][col] = xw[(k0 + row) * 48 + col];
        }
        __syncthreads();
#pragma unroll
        for (int kk = 0; kk < 32; ++kk) {
            float2 a = *(const float2*)&Ash[kk][tm * 2];
#pragma unroll
            for (int q = 0; q < 6; ++q) {
                float w = Wsh[kk][tj * 6 + q];
                acc[q][0] = fmaf(w, a.x, acc[q][0]);
                acc[q][1] = fmaf(w, a.y, acc[q][1]);
            }
        }
        __syncthreads();
    }
#pragma unroll
    for (int p = 0; p < 2; ++p) {
        int mloc = tm * 2 + p;
#pragma unroll
        for (int q = 0; q < 6; ++q) {
            int j = tj * 6 + q;
            if (j < 16) sdt[mloc][j] = acc[q][p];
            else g_xdbl[(size_t)(m0 + mloc) * 48 + j] = acc[q][p];
        }
    }
    __syncthreads();

    int mloc = tid & 63, dseg = tid >> 6;
    float rr[16];
#pragma unroll
    for (int r = 0; r < 16; ++r) rr[r] = sdt[mloc][r];

    for (int dq = 0; dq < 4; ++dq) {
#pragma unroll
        for (int r = 0; r < 8; ++r) {
            int lin = r * 256 + tid;
            int row = lin >> 7, col = lin & 127;
            shw[row][col] = dtw[row * 512 + dq * 128 + col];
        }
        if (tid < 128) shb[tid] = db[dq * 128 + tid];
        __syncthreads();
#pragma unroll 4
        for (int dd = 0; dd < 32; ++dd) {
            int dcol = dseg * 32 + dd;
            float a = shb[dcol];
#pragma unroll
            for (int r = 0; r < 16; ++r) a = fmaf(rr[r], shw[r][dcol], a);
            float sp = (a > 20.f) ? a : log1pf(__expf(a));
            g_delta[(size_t)(dq * 128 + dcol) * M_TOT + m0 + mloc] = sp;
        }
        __syncthreads();
    }
}

// ---------------- chunked scan, smem-staged ----------------------------------
__global__ void __launch_bounds__(256) k_scanA(const float* __restrict__ A_log) {
    __shared__ __align__(16) float sdl[64 * SPITCH];
    __shared__ __align__(16) float sx[64 * SPITCH];
    __shared__ __align__(16) float sB[64 * 16];
    int tid = threadIdx.x;
    int l = tid & 3, g = tid >> 2;
    int p0 = blockIdx.x * 64;
    int b = p0 >> 9, d0 = p0 & 511;
    int c = blockIdx.y;
    size_t rowbase = (size_t)b * L_SEQ + c * CLEN;

#pragma unroll
    for (int it = 0; it < 4; ++it) {
        int lin = it * 256 + tid;
        int row = lin >> 4, tq = (lin & 15) << 2;
        size_t gofs = (size_t)(d0 + row) * M_TOT + rowbase + tq;
        *(float4*)&sdl[row * SPITCH + tq] = *(const float4*)&g_delta[gofs];
        *(float4*)&sx[row * SPITCH + tq]  = ld_hl4(g_xsH, g_xsL, gofs);
    }
    {
        int t = tid >> 2, n4 = (tid & 3) << 2;
        *(float4*)&sB[t * 16 + n4] = *(const float4*)&g_xdbl[(rowbase + t) * 48 + 16 + n4];
    }
    int d = d0 + g;
    float A0 = -__expf(A_log[d * 16 + 4 * l + 0]) * LOG2E;
    float A1 = -__expf(A_log[d * 16 + 4 * l + 1]) * LOG2E;
    float A2 = -__expf(A_log[d * 16 + 4 * l + 2]) * LOG2E;
    float A3 = -__expf(A_log[d * 16 + 4 * l + 3]) * LOG2E;
    __syncthreads();

    float h0 = 0.f, h1 = 0.f, h2 = 0.f, h3 = 0.f, S = 0.f;
#pragma unroll 4
    for (int t = 0; t < CLEN; ++t) {
        float dl = sdl[g * SPITCH + t];
        float xv = sx[g * SPITCH + t];
        float4 Bv = *(const float4*)&sB[t * 16 + 4 * l];
        float e0 = ex2(dl * A0), e1 = ex2(dl * A1);
        float e2 = ex2(dl * A2), e3 = ex2(dl * A3);
        float du = dl * xv;
        h0 = fmaf(h0, e0, du * Bv.x);
        h1 = fmaf(h1, e1, du * Bv.y);
        h2 = fmaf(h2, e2, du * Bv.z);
        h3 = fmaf(h3, e3, du * Bv.w);
        S += dl;
    }
    int idx = c * 32768 + (p0 + g) * 16 + 4 * l;
    *(float4*)&g_P[idx]  = make_float4(ex2(A0 * S), ex2(A1 * S), ex2(A2 * S), ex2(A3 * S));
    *(float4*)&g_Lh[idx] = make_float4(h0, h1, h2, h3);
}

// Phase B: scan across chunks.
__global__ void __launch_bounds__(256) k_scanB() {
    int gid = blockIdx.x * 256 + threadIdx.x;
    float h = 0.f;
#pragma unroll 8
    for (int c = 0; c < NCHUNK; ++c) {
        int idx = c * 32768 + gid;
        g_H[idx] = h;
        h = fmaf(h, g_P[idx], g_Lh[idx]);
    }
}

// Phase C: recompute + silu(z) gate + coalesced bf16 y store.
#define SMEM_SCANC ((4 * 64 * SPITCH + 2 * 64 * 16) * 4)
__global__ void __launch_bounds__(256) k_scanC(const float* __restrict__ A_log,
                                               const float* __restrict__ Dp_) {
    extern __shared__ __align__(16) float smc[];
    float* sdl = smc;                        // [64][SPITCH]
    float* sx  = sdl + 64 * SPITCH;
    float* sz  = sx  + 64 * SPITCH;          // raw z, reconstructed fp32
    float* sy  = sz  + 64 * SPITCH;          // [64][SPITCH]
    float* sB  = sy  + 64 * SPITCH;          // [64*16]
    float* sC  = sB  + 64 * 16;

    int tid = threadIdx.x;
    int l = tid & 3, g = tid >> 2;
    int p0 = blockIdx.x * 64;
    int b = p0 >> 9, d0 = p0 & 511;
    int c = blockIdx.y;
    size_t rowbase = (size_t)b * L_SEQ + c * CLEN;

#pragma unroll
    for (int it = 0; it < 4; ++it) {
        int lin = it * 256 + tid;
        int row = lin >> 4, tq = (lin & 15) << 2;
        size_t gofs = (size_t)(d0 + row) * M_TOT + rowbase + tq;
        *(float4*)&sdl[row * SPITCH + tq] = *(const float4*)&g_delta[gofs];
        *(float4*)&sx[row * SPITCH + tq]  = ld_hl4(g_xsH, g_xsL, gofs);
        *(float4*)&sz[row * SPITCH + tq]  = ld_hl4(g_zsH, g_zsL, gofs);
    }
    {
        int t = tid >> 2, n4 = (tid & 3) << 2;
        *(float4*)&sB[t * 16 + n4] = *(const float4*)&g_xdbl[(rowbase + t) * 48 + 16 + n4];
        *(float4*)&sC[t * 16 + n4] = *(const float4*)&g_xdbl[(rowbase + t) * 48 + 32 + n4];
    }
    int d = d0 + g;
    float A0 = -__expf(A_log[d * 16 + 4 * l + 0]) * LOG2E;
    float A1 = -__expf(A_log[d * 16 + 4 * l + 1]) * LOG2E;
    float A2 = -__expf(A_log[d * 16 + 4 * l + 2]) * LOG2E;
    float A3 = -__expf(A_log[d * 16 + 4 * l + 3]) * LOG2E;
    float Dv = Dp_[d];
    __syncthreads();

    int idx = c * 32768 + (p0 + g) * 16 + 4 * l;
    float4 hh = *(const float4*)&g_H[idx];
    float h0 = hh.x, h1 = hh.y, h2 = hh.z, h3 = hh.w;

#pragma unroll 4
    for (int t = 0; t < CLEN; ++t) {
        float dl = sdl[g * SPITCH + t];
        float xv = sx[g * SPITCH + t];
        float4 Bv = *(const float4*)&sB[t * 16 + 4 * l];
        float4 Cv = *(const float4*)&sC[t * 16 + 4 * l];
        float e0 = ex2(dl * A0), e1 = ex2(dl * A1);
        float e2 = ex2(dl * A2), e3 = ex2(dl * A3);
        float du = dl * xv;
        h0 = fmaf(h0, e0, du * Bv.x);
        h1 = fmaf(h1, e1, du * Bv.y);
        h2 = fmaf(h2, e2, du * Bv.z);
        h3 = fmaf(h3, e3, du * Bv.w);
        float pr = h0 * Cv.x;
        pr = fmaf(h1, Cv.y, pr);
        pr = fmaf(h2, Cv.z, pr);
        pr = fmaf(h3, Cv.w, pr);
        pr += __shfl_xor_sync(0xffffffffu, pr, 1);
        pr += __shfl_xor_sync(0xffffffffu, pr, 2);
        if (l == 0) {
            float zv = sz[g * SPITCH + t];
            float yv = fmaf(xv, Dv, pr);
            yv = yv * zv * (1.f / (1.f + __expf(-zv)));
            sy[g * SPITCH + t] = yv;
        }
    }
    __syncthreads();

#pragma unroll
    for (int i = 0; i < 16; ++i) {
        int elem = i * 256 + tid;
        int row = elem >> 6, t = elem & 63;
        float yv = sy[row * SPITCH + t];
        __nv_bfloat16 yh = __float2bfloat16(yv);
        __nv_bfloat16 yl = __float2bfloat16(yv - __bfloat162float(yh));
        size_t gof = (size_t)(d0 + row) * M_TOT + rowbase + t;
        g_yH[gof] = yh;
        g_yL[gof] = yl;
    }
}

// ---------------- launch -----------------------------------------------------
extern "C" void kernel_launch(void* const* d_in, const int* in_sizes, int n_in,
                              void* d_out, int out_size) {
    const float* input  = (const float*)d_in[0];
    const float* input2 = (const float*)d_in[1];
    const float* ln_g   = (const float*)d_in[2];
    const float* ln_b   = (const float*)d_in[3];
    const float* outp_w = (const float*)d_in[4];
    const float* outp_b = (const float*)d_in[5];
    const float* inproj = (const float*)d_in[6];
    const float* conv_w = (const float*)d_in[7];
    const float* conv_b = (const float*)d_in[8];
    const float* xproj  = (const float*)d_in[9];
    const float* dtw    = (const float*)d_in[10];
    const float* dtb    = (const float*)d_in[11];
    const float* A_log  = (const float*)d_in[12];
    const float* Dp     = (const float*)d_in[13];
    const float* mow    = (const float*)d_in[14];
    float* out = (float*)d_out;

    __nv_bfloat16 *wtH, *wtL, *wcH, *wcL, *xnH, *xnL, *yH, *yL;
    float *xz;
    cudaGetSymbolAddress((void**)&wtH, g_WtH);
    cudaGetSymbolAddress((void**)&wtL, g_WtL);
    cudaGetSymbolAddress((void**)&wcH, g_WcH);
    cudaGetSymbolAddress((void**)&wcL, g_WcL);
    cudaGetSymbolAddress((void**)&xnH, g_XnH);
    cudaGetSymbolAddress((void**)&xnL, g_XnL);
    cudaGetSymbolAddress((void**)&yH, g_yH);
    cudaGetSymbolAddress((void**)&yL, g_yL);
    cudaGetSymbolAddress((void**)&xz, g_xz);

    cudaFuncSetAttribute(k_mma<256, false>,
                         cudaFuncAttributeMaxDynamicSharedMemorySize, SMEM_MMA);
    cudaFuncSetAttribute(k_mma<512, true>,
                         cudaFuncAttributeMaxDynamicSharedMemorySize, SMEM_MMA);
    cudaFuncSetAttribute(k_scanC,
                         cudaFuncAttributeMaxDynamicSharedMemorySize, SMEM_SCANC);

    k_wt<<<dim3(32, 8), dim3(32, 8)>>>(inproj);
    k_wc<<<512, 128>>>(mow, outp_w);
    k_ln<<<256, 256>>>(input, input2, ln_g, ln_b);
    k_mma<256, false><<<dim3(128, 8), 256, SMEM_MMA>>>(wtH, wtL, xnH, xnL, xz, nullptr);
    k_conv<<<dim3(16, 512), 256>>>(conv_w, conv_b);
    k_xproj<<<256, 256>>>(xproj, dtw, dtb);
    k_scanA<<<dim3(32, 64), 256>>>(A_log);
    k_scanB<<<128, 256>>>();
    k_scanC<<<dim3(32, 64), 256, SMEM_SCANC>>>(A_log, Dp);
    k_mma<512, true><<<dim3(128, 1), 256, SMEM_MMA>>>(wcH, wcL, yH, yL, out, outp_b);
}

// round 16
// speedup vs baseline: 1.0483x; 1.0483x over previous
#include <cuda_runtime.h>
#include <cuda_bf16.h>
#include <cstdint>

typedef unsigned long long ull;

#define M_TOT 16384   // B * L
#define L_SEQ 4096
#define NCHUNK 64
#define CLEN 64
#define LOG2E 1.4426950408889634f
#define SPITCH 68     // scan smem row pitch (floats): 16B-aligned, conflict-free

// ---------------- scratch ----------------------------------------------------
__device__ __align__(16) float g_xdbl[M_TOT * 48];    // x_proj out, (m, j)
__device__ __align__(16) float g_delta[512 * M_TOT];  // softplus, (d, m)
__device__ __align__(16) float g_P[NCHUNK * 2048 * 16];
__device__ __align__(16) float g_Lh[NCHUNK * 2048 * 16];
__device__ __align__(16) float g_H[NCHUNK * 2048 * 16];
__device__ __align__(16) __nv_bfloat16 g_xpH[512 * M_TOT];  // in_proj x-branch hi, (d,m)
__device__ __align__(16) __nv_bfloat16 g_xpL[512 * M_TOT];  // in_proj x-branch lo
__device__ __align__(16) __nv_bfloat16 g_xsH[512 * M_TOT];  // conv+silu hi, (d,m)
__device__ __align__(16) __nv_bfloat16 g_xsL[512 * M_TOT];  // conv+silu lo
__device__ __align__(16) __nv_bfloat16 g_zsH[512 * M_TOT];  // silu(z) hi, (d,m)
__device__ __align__(16) __nv_bfloat16 g_zsL[512 * M_TOT];  // silu(z) lo
__device__ __align__(16) __nv_bfloat16 g_XnH[256 * M_TOT];
__device__ __align__(16) __nv_bfloat16 g_XnL[256 * M_TOT];
__device__ __align__(16) __nv_bfloat16 g_yH[512 * M_TOT];
__device__ __align__(16) __nv_bfloat16 g_yL[512 * M_TOT];
__device__ __align__(16) __nv_bfloat16 g_WtH[1024 * 256];
__device__ __align__(16) __nv_bfloat16 g_WtL[1024 * 256];
__device__ __align__(16) __nv_bfloat16 g_WcH[128 * 512];
__device__ __align__(16) __nv_bfloat16 g_WcL[128 * 512];

// ---------------- helpers ----------------------------------------------------
__device__ __forceinline__ uint32_t smem_u32(const void* p) {
    uint32_t a;
    asm("{ .reg .u64 t; cvta.to.shared.u64 t, %1; cvt.u32.u64 %0, t; }" : "=r"(a) : "l"(p));
    return a;
}
__device__ __forceinline__ float ex2(float x) {
    float r;
    asm("ex2.approx.f32 %0, %1;" : "=f"(r) : "f"(x));
    return r;
}
__device__ __forceinline__ void ldsm4(uint32_t* r, uint32_t addr) {
    asm volatile("ldmatrix.sync.aligned.m8n8.x4.shared.b16 {%0,%1,%2,%3}, [%4];"
        : "=r"(r[0]), "=r"(r[1]), "=r"(r[2]), "=r"(r[3]) : "r"(addr));
}
__device__ __forceinline__ void ldsm4t(uint32_t* r, uint32_t addr) {
    asm volatile("ldmatrix.sync.aligned.m8n8.x4.trans.shared.b16 {%0,%1,%2,%3}, [%4];"
        : "=r"(r[0]), "=r"(r[1]), "=r"(r[2]), "=r"(r[3]) : "r"(addr));
}
__device__ __forceinline__ void mma_bf16(float* d, const uint32_t* a, const uint32_t* b) {
    asm volatile("mma.sync.aligned.m16n8k16.row.col.f32.bf16.bf16.f32 "
        "{%0,%1,%2,%3}, {%4,%5,%6,%7}, {%8,%9}, {%0,%1,%2,%3};"
        : "+f"(d[0]), "+f"(d[1]), "+f"(d[2]), "+f"(d[3])
        : "r"(a[0]), "r"(a[1]), "r"(a[2]), "r"(a[3]), "r"(b[0]), "r"(b[1]));
}
// load 4 floats reconstructed from bf16 hi/lo arrays (idx 4-elem aligned)
__device__ __forceinline__ float4 ld_hl4(const __nv_bfloat16* __restrict__ H,
                                         const __nv_bfloat16* __restrict__ L, size_t idx) {
    uint2 uh = *(const uint2*)(H + idx);
    uint2 ul = *(const uint2*)(L + idx);
    __nv_bfloat162 a, b, c, d;
    *(uint32_t*)&a = uh.x; *(uint32_t*)&b = uh.y;
    *(uint32_t*)&c = ul.x; *(uint32_t*)&d = ul.y;
    float2 fa = __bfloat1622float2(a), fb = __bfloat1622float2(b);
    float2 fc = __bfloat1622float2(c), fd = __bfloat1622float2(d);
    return make_float4(fa.x + fc.x, fa.y + fc.y, fb.x + fd.x, fb.y + fd.y);
}
// store 2 floats split hi/lo (idx 2-elem aligned)
__device__ __forceinline__ void st_hl2(__nv_bfloat16* __restrict__ H,
                                       __nv_bfloat16* __restrict__ L,
                                       size_t idx, float2 v) {
    __nv_bfloat16 h0 = __float2bfloat16(v.x), h1 = __float2bfloat16(v.y);
    __nv_bfloat16 l0 = __float2bfloat16(v.x - __bfloat162float(h0));
    __nv_bfloat16 l1 = __float2bfloat16(v.y - __bfloat162float(h1));
    __nv_bfloat162 hh; hh.x = h0; hh.y = h1;
    __nv_bfloat162 ll; ll.x = l0; ll.y = l1;
    *(__nv_bfloat162*)(H + idx) = hh;
    *(__nv_bfloat162*)(L + idx) = ll;
}
#define CPA16(dst, src) asm volatile("cp.async.cg.shared.global [%0], [%1], 16;" :: "r"(dst), "l"(src))
#define CPA_COMMIT()    asm volatile("cp.async.commit_group;" ::: "memory")
#define CPA_WAIT(n)     asm volatile("cp.async.wait_group %0;" :: "n"(n) : "memory")

// ---------------- K_wt: split-transpose in_proj_w -> [n][k] bf16 ------------
__global__ void k_wt(const float* __restrict__ W) {
    __shared__ float t[32][33];
    int n0 = blockIdx.x * 32, k0 = blockIdx.y * 32;
    int x = threadIdx.x, y0 = threadIdx.y;
    for (int yy = y0; yy < 32; yy += 8) t[yy][x] = W[(k0 + yy) * 1024 + n0 + x];
    __syncthreads();
    for (int yy = y0; yy < 32; yy += 8) {
        float v = t[x][yy];
        __nv_bfloat16 h = __float2bfloat16(v);
        __nv_bfloat16 l = __float2bfloat16(v - __bfloat162float(h));
        g_WtH[(size_t)(n0 + yy) * 256 + k0 + x] = h;
        g_WtL[(size_t)(n0 + yy) * 256 + k0 + x] = l;
    }
}

// ---------------- K_wc: (mow @ outp_w)^T split ------------------------------
__global__ void k_wc(const float* __restrict__ mw, const float* __restrict__ ow) {
    int d = blockIdx.x, e = threadIdx.x;
    float acc = 0.f;
#pragma unroll 8
    for (int c = 0; c < 256; ++c)
        acc = fmaf(mw[d * 256 + c], ow[c * 128 + e], acc);
    __nv_bfloat16 h = __float2bfloat16(acc);
    __nv_bfloat16 l = __float2bfloat16(acc - __bfloat162float(h));
    g_WcH[(size_t)e * 512 + d] = h;
    g_WcL[(size_t)e * 512 + d] = l;
}

// ---------------- K1: concat + LN, 4 threads per token ----------------------
__global__ void __launch_bounds__(256) k_ln(const float* __restrict__ in1,
                                            const float* __restrict__ in2,
                                            const float* __restrict__ gg,
                                            const float* __restrict__ bb) {
    __shared__ float sg[256], sb[256];
    __shared__ float red[2][4][64];
    int tid = threadIdx.x;
    int q = tid >> 6, ml = tid & 63;
    sg[tid] = gg[tid]; sb[tid] = bb[tid];

    int m = blockIdx.x * 64 + ml;
    int b = m >> 12, t = m & 4095;
    const float* src = ((q < 2) ? in1 : in2) + (size_t)b * 128 * 4096 + t;
    int c0 = (q & 1) * 64;

    float vals[64];
    float s = 0.f, s2 = 0.f;
#pragma unroll
    for (int i = 0; i < 64; ++i) {
        float v = src[(size_t)(c0 + i) * 4096];
        vals[i] = v; s += v; s2 += v * v;
    }
    red[0][q][ml] = s; red[1][q][ml] = s2;
    __syncthreads();
    s  = red[0][0][ml] + red[0][1][ml] + red[0][2][ml] + red[0][3][ml];
    s2 = red[1][0][ml] + red[1][1][ml] + red[1][2][ml] + red[1][3][ml];
    float mu = s * (1.f / 256.f);
    float var = s2 * (1.f / 256.f) - mu * mu;
    float rs = rsqrtf(var + 1e-5f);

    int cbase = q * 64;
#pragma unroll
    for (int i = 0; i < 64; ++i) {
        int c = cbase + i;
        float o = (vals[i] - mu) * rs * sg[c] + sb[c];
        __nv_bfloat16 h = __float2bfloat16(o);
        __nv_bfloat16 l = __float2bfloat16(o - __bfloat162float(h));
        g_XnH[(size_t)c * M_TOT + m] = h;
        g_XnL[(size_t)c * M_TOT + m] = l;
    }
}

// ---------------- warp-MMA GEMM: split bf16, cp.async 3-stage ----------------
// in_proj epilogue: n<512 -> raw x bf16 H/L; n>=512 -> silu(z) bf16 H/L.
#define STG_SZ 65536
#define SMEM_MMA 196608

template<int KT, bool IS_OUT>
__global__ void __launch_bounds__(256) k_mma(
    const __nv_bfloat16* __restrict__ AH, const __nv_bfloat16* __restrict__ AL,
    const __nv_bfloat16* __restrict__ BH, const __nv_bfloat16* __restrict__ BL,
    float* __restrict__ outp, const float* __restrict__ bias)
{
    extern __shared__ __align__(16) char sm[];
    const int tid = threadIdx.x;
    const int lane = tid & 31, wid = tid >> 5;
    const int wr = wid & 1, wc = wid >> 1;
    const int m0 = blockIdx.x * 128, n0 = blockIdx.y * 128;
    const uint32_t smb = smem_u32(sm);
    const int NK = KT / 64;

    float acc[4][4][4];
#pragma unroll
    for (int i = 0; i < 4; ++i)
#pragma unroll
        for (int j = 0; j < 4; ++j)
#pragma unroll
            for (int p = 0; p < 4; ++p) acc[i][j][p] = 0.f;

    auto stage = [&](int kc, int stg) {
        uint32_t base = smb + stg * STG_SZ;
#pragma unroll
        for (int it = 0; it < 4; ++it) {
            int cid = it * 256 + tid;
            int row = cid >> 3, seg = cid & 7;
            size_t gof = (size_t)(n0 + row) * KT + kc * 64 + seg * 8;
            uint32_t off = row * 128 + ((seg ^ (row & 7)) << 4);
            CPA16(base + off, AH + gof);
            CPA16(base + 16384 + off, AL + gof);
        }
#pragma unroll
        for (int it = 0; it < 4; ++it) {
            int cid = it * 256 + tid;
            int k = cid >> 4, mseg = cid & 15;
            size_t gof = (size_t)(kc * 64 + k) * M_TOT + m0 + mseg * 8;
            uint32_t off = k * 256 + ((mseg ^ (k & 7)) << 4);
            CPA16(base + 32768 + off, BH + gof);
            CPA16(base + 49152 + off, BL + gof);
        }
    };

    stage(0, 0); CPA_COMMIT();
    if (NK > 1) { stage(1, 1); CPA_COMMIT(); }

    for (int kc = 0; kc < NK; ++kc) {
        if (kc + 1 < NK) CPA_WAIT(1); else CPA_WAIT(0);
        __syncthreads();
        if (kc + 2 < NK) { stage(kc + 2, (kc + 2) % 3); CPA_COMMIT(); }

        uint32_t sa_h = smb + (kc % 3) * STG_SZ;
        uint32_t sa_l = sa_h + 16384;
        uint32_t sb_h = sa_h + 32768;
        uint32_t sb_l = sa_h + 49152;

#pragma unroll
        for (int ks = 0; ks < 4; ++ks) {
            uint32_t afh[4][4], afl[4][4];
            {
                int row = wr * 64 + (lane & 7) + ((lane >> 3) & 1) * 8;
                int seg = ks * 2 + (lane >> 4);
#pragma unroll
                for (int rt = 0; rt < 4; ++rt) {
                    int r = row + rt * 16;
                    uint32_t off = r * 128 + ((seg ^ (r & 7)) << 4);
                    ldsm4(afh[rt], sa_h + off);
                    ldsm4(afl[rt], sa_l + off);
                }
            }
            uint32_t bfh[4][2], bfl[4][2];
            {
                int k = ks * 16 + (lane & 7) + ((lane >> 3) & 1) * 8;
#pragma unroll
                for (int half = 0; half < 2; ++half) {
                    int mseg = wc * 4 + half * 2 + (lane >> 4);
                    uint32_t off = k * 256 + ((mseg ^ (k & 7)) << 4);
                    uint32_t r[4];
                    ldsm4t(r, sb_h + off);
                    bfh[half * 2][0] = r[0]; bfh[half * 2][1] = r[1];
                    bfh[half * 2 + 1][0] = r[2]; bfh[half * 2 + 1][1] = r[3];
                    ldsm4t(r, sb_l + off);
                    bfl[half * 2][0] = r[0]; bfl[half * 2][1] = r[1];
                    bfl[half * 2 + 1][0] = r[2]; bfl[half * 2 + 1][1] = r[3];
                }
            }
#pragma unroll
            for (int rt = 0; rt < 4; ++rt)
#pragma unroll
                for (int ct = 0; ct < 4; ++ct) {
                    mma_bf16(acc[rt][ct], afh[rt], bfh[ct]);
                    mma_bf16(acc[rt][ct], afh[rt], bfl[ct]);
                    mma_bf16(acc[rt][ct], afl[rt], bfh[ct]);
                }
        }
    }

    const bool ZPART = (!IS_OUT) && (n0 >= 512);
#pragma unroll
    for (int rt = 0; rt < 4; ++rt) {
        int row0 = n0 + wr * 64 + rt * 16 + (lane >> 2);
        int row1 = row0 + 8;
        float b0 = 0.f, b1 = 0.f;
        if (IS_OUT) { b0 = bias[row0]; b1 = bias[row1]; }
#pragma unroll
        for (int ct = 0; ct < 4; ++ct) {
            int col = m0 + wc * 32 + ct * 8 + (lane & 3) * 2;
            float2 v0 = make_float2(acc[rt][ct][0] + b0, acc[rt][ct][1] + b0);
            float2 v1 = make_float2(acc[rt][ct][2] + b1, acc[rt][ct][3] + b1);
            if (IS_OUT) {
                int bb = col >> 12, t = col & 4095;
                *(float2*)&outp[((size_t)(bb * 128 + row0) << 12) + t] = v0;
                *(float2*)&outp[((size_t)(bb * 128 + row1) << 12) + t] = v1;
            } else if (ZPART) {
                float2 s0 = make_float2(v0.x / (1.f + __expf(-v0.x)),
                                        v0.y / (1.f + __expf(-v0.y)));
                float2 s1 = make_float2(v1.x / (1.f + __expf(-v1.x)),
                                        v1.y / (1.f + __expf(-v1.y)));
                st_hl2(g_zsH, g_zsL, (size_t)(row0 - 512) * M_TOT + col, s0);
                st_hl2(g_zsH, g_zsL, (size_t)(row1 - 512) * M_TOT + col, s1);
            } else {
                st_hl2(g_xpH, g_xpL, (size_t)row0 * M_TOT + col, v0);
                st_hl2(g_xpH, g_xpL, (size_t)row1 * M_TOT + col, v1);
            }
        }
    }
}

// ---------------- K3: causal dwconv(4) + bias + silu -> bf16 H/L ------------
__global__ void k_conv(const float* __restrict__ cw, const float* __restrict__ cb) {
    int d = blockIdx.y;
    int m4 = (blockIdx.x * 256 + threadIdx.x) * 4;
    int t4 = m4 & 4095;
    size_t rowb = (size_t)d * M_TOT;
    float4 v = ld_hl4(g_xpH, g_xpL, rowb + m4);
    float4 vp = (t4 == 0) ? make_float4(0.f, 0.f, 0.f, 0.f)
                          : ld_hl4(g_xpH, g_xpL, rowb + m4 - 4);
    float w0 = cw[d * 4 + 0], w1 = cw[d * 4 + 1], w2 = cw[d * 4 + 2], w3 = cw[d * 4 + 3];
    float bia = cb[d];
    float4 o;
    o.x = bia + w3 * v.x + w2 * vp.w + w1 * vp.z + w0 * vp.y;
    o.y = bia + w3 * v.y + w2 * v.x + w1 * vp.w + w0 * vp.z;
    o.z = bia + w3 * v.z + w2 * v.y + w1 * v.x + w0 * vp.w;
    o.w = bia + w3 * v.w + w2 * v.z + w1 * v.y + w0 * v.x;
    o.x = o.x / (1.f + __expf(-o.x));
    o.y = o.y / (1.f + __expf(-o.y));
    o.z = o.z / (1.f + __expf(-o.z));
    o.w = o.w / (1.f + __expf(-o.w));
    st_hl2(g_xsH, g_xsL, rowb + m4, make_float2(o.x, o.y));
    st_hl2(g_xsH, g_xsL, rowb + m4 + 2, make_float2(o.z, o.w));
}

// ---------------- K4: x_proj + dt_proj fused, m-tile 64, grid 256 -----------
__global__ void __launch_bounds__(256) k_xproj(const float* __restrict__ xw,
                                               const float* __restrict__ dtw,
                                               const float* __restrict__ db) {
    __shared__ __align__(16) float Ash[32][64];
    __shared__ float Wsh[32][48];
    __shared__ float sdt[64][17];
    __shared__ float shw[16][128];
    __shared__ float shb[128];
    int tid = threadIdx.x;
    int m0 = blockIdx.x * 64;
    int tj = tid >> 5, tm = tid & 31;
    float acc[6][2] = {};

    for (int k0 = 0; k0 < 512; k0 += 32) {
#pragma unroll
        for (int r = 0; r < 2; ++r) {
            int lin = r * 256 + tid;
            int row = lin >> 4, c4 = (lin & 15) << 2;
            float4 f = ld_hl4(g_xsH, g_xsL, (size_t)(k0 + row) * M_TOT + m0 + c4);
            *(float4*)&Ash[row][c4] = f;
        }
#pragma unroll
        for (int r = 0; r < 6; ++r) {
            int lin = r * 256 + tid;
            int row = lin / 48, col = lin % 48;
            Wsh[row][col] = xw[(k0 + row) * 48 + col];
        }
        __syncthreads();
#pragma unroll
        for (int kk = 0; kk < 32; ++kk) {
            float2 a = *(const float2*)&Ash[kk][tm * 2];
#pragma unroll
            for (int q = 0; q < 6; ++q) {
                float w = Wsh[kk][tj * 6 + q];
                acc[q][0] = fmaf(w, a.x, acc[q][0]);
                acc[q][1] = fmaf(w, a.y, acc[q][1]);
            }
        }
        __syncthreads();
    }
#pragma unroll
    for (int p = 0; p < 2; ++p) {
        int mloc = tm * 2 + p;
#pragma unroll
        for (int q = 0; q < 6; ++q) {
            int j = tj * 6 + q;
            if (j < 16) sdt[mloc][j] = acc[q][p];
            else g_xdbl[(size_t)(m0 + mloc) * 48 + j] = acc[q][p];
        }
    }
    __syncthreads();

    int mloc = tid & 63, dseg = tid >> 6;
    float rr[16];
#pragma unroll
    for (int r = 0; r < 16; ++r) rr[r] = sdt[mloc][r];

    for (int dq = 0; dq < 4; ++dq) {
#pragma unroll
        for (int r = 0; r < 8; ++r) {
            int lin = r * 256 + tid;
            int row = lin >> 7, col = lin & 127;
            shw[row][col] = dtw[row * 512 + dq * 128 + col];
        }
        if (tid < 128) shb[tid] = db[dq * 128 + tid];
        __syncthreads();
#pragma unroll 4
        for (int dd = 0; dd < 32; ++dd) {
            int dcol = dseg * 32 + dd;
            float a = shb[dcol];
#pragma unroll
            for (int r = 0; r < 16; ++r) a = fmaf(rr[r], shw[r][dcol], a);
            float sp = (a > 20.f) ? a : log1pf(__expf(a));
            g_delta[(size_t)(dq * 128 + dcol) * M_TOT + m0 + mloc] = sp;
        }
        __syncthreads();
    }
}

// ---------------- chunked scan, smem-staged ----------------------------------
__global__ void __launch_bounds__(256) k_scanA(const float* __restrict__ A_log) {
    __shared__ __align__(16) float sdl[64 * SPITCH];
    __shared__ __align__(16) float sx[64 * SPITCH];
    __shared__ __align__(16) float sB[64 * 16];
    int tid = threadIdx.x;
    int l = tid & 3, g = tid >> 2;
    int p0 = blockIdx.x * 64;
    int b = p0 >> 9, d0 = p0 & 511;
    int c = blockIdx.y;
    size_t rowbase = (size_t)b * L_SEQ + c * CLEN;

#pragma unroll
    for (int it = 0; it < 4; ++it) {
        int lin = it * 256 + tid;
        int row = lin >> 4, tq = (lin & 15) << 2;
        size_t gofs = (size_t)(d0 + row) * M_TOT + rowbase + tq;
        *(float4*)&sdl[row * SPITCH + tq] = *(const float4*)&g_delta[gofs];
        *(float4*)&sx[row * SPITCH + tq]  = ld_hl4(g_xsH, g_xsL, gofs);
    }
    {
        int t = tid >> 2, n4 = (tid & 3) << 2;
        *(float4*)&sB[t * 16 + n4] = *(const float4*)&g_xdbl[(rowbase + t) * 48 + 16 + n4];
    }
    int d = d0 + g;
    float A0 = -__expf(A_log[d * 16 + 4 * l + 0]) * LOG2E;
    float A1 = -__expf(A_log[d * 16 + 4 * l + 1]) * LOG2E;
    float A2 = -__expf(A_log[d * 16 + 4 * l + 2]) * LOG2E;
    float A3 = -__expf(A_log[d * 16 + 4 * l + 3]) * LOG2E;
    __syncthreads();

    float h0 = 0.f, h1 = 0.f, h2 = 0.f, h3 = 0.f, S = 0.f;
#pragma unroll 4
    for (int t = 0; t < CLEN; ++t) {
        float dl = sdl[g * SPITCH + t];
        float xv = sx[g * SPITCH + t];
        float4 Bv = *(const float4*)&sB[t * 16 + 4 * l];
        float e0 = ex2(dl * A0), e1 = ex2(dl * A1);
        float e2 = ex2(dl * A2), e3 = ex2(dl * A3);
        float du = dl * xv;
        h0 = fmaf(h0, e0, du * Bv.x);
        h1 = fmaf(h1, e1, du * Bv.y);
        h2 = fmaf(h2, e2, du * Bv.z);
        h3 = fmaf(h3, e3, du * Bv.w);
        S += dl;
    }
    int idx = c * 32768 + (p0 + g) * 16 + 4 * l;
    *(float4*)&g_P[idx]  = make_float4(ex2(A0 * S), ex2(A1 * S), ex2(A2 * S), ex2(A3 * S));
    *(float4*)&g_Lh[idx] = make_float4(h0, h1, h2, h3);
}

// Phase B: scan across chunks.
__global__ void __launch_bounds__(256) k_scanB() {
    int gid = blockIdx.x * 256 + threadIdx.x;
    float h = 0.f;
#pragma unroll 8
    for (int c = 0; c < NCHUNK; ++c) {
        int idx = c * 32768 + gid;
        g_H[idx] = h;
        h = fmaf(h, g_P[idx], g_Lh[idx]);
    }
}

// Phase C: recompute + gate (pre-siluted z) + coalesced bf16 y store.
#define SMEM_SCANC ((4 * 64 * SPITCH + 2 * 64 * 16) * 4)
__global__ void __launch_bounds__(256) k_scanC(const float* __restrict__ A_log,
                                               const float* __restrict__ Dp_) {
    extern __shared__ __align__(16) float smc[];
    float* sdl = smc;                        // [64][SPITCH]
    float* sx  = sdl + 64 * SPITCH;
    float* sz  = sx  + 64 * SPITCH;          // silu(z), reconstructed fp32
    float* sy  = sz  + 64 * SPITCH;          // [64][SPITCH]
    float* sB  = sy  + 64 * SPITCH;          // [64*16]
    float* sC  = sB  + 64 * 16;

    int tid = threadIdx.x;
    int l = tid & 3, g = tid >> 2;
    int p0 = blockIdx.x * 64;
    int b = p0 >> 9, d0 = p0 & 511;
    int c = blockIdx.y;
    size_t rowbase = (size_t)b * L_SEQ + c * CLEN;

#pragma unroll
    for (int it = 0; it < 4; ++it) {
        int lin = it * 256 + tid;
        int row = lin >> 4, tq = (lin & 15) << 2;
        size_t gofs = (size_t)(d0 + row) * M_TOT + rowbase + tq;
        *(float4*)&sdl[row * SPITCH + tq] = *(const float4*)&g_delta[gofs];
        *(float4*)&sx[row * SPITCH + tq]  = ld_hl4(g_xsH, g_xsL, gofs);
        *(float4*)&sz[row * SPITCH + tq]  = ld_hl4(g_zsH, g_zsL, gofs);
    }
    {
        int t = tid >> 2, n4 = (tid & 3) << 2;
        *(float4*)&sB[t * 16 + n4] = *(const float4*)&g_xdbl[(rowbase + t) * 48 + 16 + n4];
        *(float4*)&sC[t * 16 + n4] = *(const float4*)&g_xdbl[(rowbase + t) * 48 + 32 + n4];
    }
    int d = d0 + g;
    float A0 = -__expf(A_log[d * 16 + 4 * l + 0]) * LOG2E;
    float A1 = -__expf(A_log[d * 16 + 4 * l + 1]) * LOG2E;
    float A2 = -__expf(A_log[d * 16 + 4 * l + 2]) * LOG2E;
    float A3 = -__expf(A_log[d * 16 + 4 * l + 3]) * LOG2E;
    float Dv = Dp_[d];
    __syncthreads();

    int idx = c * 32768 + (p0 + g) * 16 + 4 * l;
    float4 hh = *(const float4*)&g_H[idx];
    float h0 = hh.x, h1 = hh.y, h2 = hh.z, h3 = hh.w;

#pragma unroll 4
    for (int t = 0; t < CLEN; ++t) {
        float dl = sdl[g * SPITCH + t];
        float xv = sx[g * SPITCH + t];
        float4 Bv = *(const float4*)&sB[t * 16 + 4 * l];
        float4 Cv = *(const float4*)&sC[t * 16 + 4 * l];
        float e0 = ex2(dl * A0), e1 = ex2(dl * A1);
        float e2 = ex2(dl * A2), e3 = ex2(dl * A3);
        float du = dl * xv;
        h0 = fmaf(h0, e0, du * Bv.x);
        h1 = fmaf(h1, e1, du * Bv.y);
        h2 = fmaf(h2, e2, du * Bv.z);
        h3 = fmaf(h3, e3, du * Bv.w);
        float pr = h0 * Cv.x;
        pr = fmaf(h1, Cv.y, pr);
        pr = fmaf(h2, Cv.z, pr);
        pr = fmaf(h3, Cv.w, pr);
        pr += __shfl_xor_sync(0xffffffffu, pr, 1);
        pr += __shfl_xor_sync(0xffffffffu, pr, 2);
        if (l == 0) {
            float yv = fmaf(xv, Dv, pr);
            sy[g * SPITCH + t] = yv * sz[g * SPITCH + t];   // z already silu'd
        }
    }
    __syncthreads();

#pragma unroll
    for (int i = 0; i < 16; ++i) {
        int elem = i * 256 + tid;
        int row = elem >> 6, t = elem & 63;
        float yv = sy[row * SPITCH + t];
        __nv_bfloat16 yh = __float2bfloat16(yv);
        __nv_bfloat16 yl = __float2bfloat16(yv - __bfloat162float(yh));
        size_t gof = (size_t)(d0 + row) * M_TOT + rowbase + t;
        g_yH[gof] = yh;
        g_yL[gof] = yl;
    }
}

// ---------------- launch -----------------------------------------------------
extern "C" void kernel_launch(void* const* d_in, const int* in_sizes, int n_in,
                              void* d_out, int out_size) {
    const float* input  = (const float*)d_in[0];
    const float* input2 = (const float*)d_in[1];
    const float* ln_g   = (const float*)d_in[2];
    const float* ln_b   = (const float*)d_in[3];
    const float* outp_w = (const float*)d_in[4];
    const float* outp_b = (const float*)d_in[5];
    const float* inproj = (const float*)d_in[6];
    const float* conv_w = (const float*)d_in[7];
    const float* conv_b = (const float*)d_in[8];
    const float* xproj  = (const float*)d_in[9];
    const float* dtw    = (const float*)d_in[10];
    const float* dtb    = (const float*)d_in[11];
    const float* A_log  = (const float*)d_in[12];
    const float* Dp     = (const float*)d_in[13];
    const float* mow    = (const float*)d_in[14];
    float* out = (float*)d_out;

    __nv_bfloat16 *wtH, *wtL, *wcH, *wcL, *xnH, *xnL, *yH, *yL;
    cudaGetSymbolAddress((void**)&wtH, g_WtH);
    cudaGetSymbolAddress((void**)&wtL, g_WtL);
    cudaGetSymbolAddress((void**)&wcH, g_WcH);
    cudaGetSymbolAddress((void**)&wcL, g_WcL);
    cudaGetSymbolAddress((void**)&xnH, g_XnH);
    cudaGetSymbolAddress((void**)&xnL, g_XnL);
    cudaGetSymbolAddress((void**)&yH, g_yH);
    cudaGetSymbolAddress((void**)&yL, g_yL);

    cudaFuncSetAttribute(k_mma<256, false>,
                         cudaFuncAttributeMaxDynamicSharedMemorySize, SMEM_MMA);
    cudaFuncSetAttribute(k_mma<512, true>,
                         cudaFuncAttributeMaxDynamicSharedMemorySize, SMEM_MMA);
    cudaFuncSetAttribute(k_scanC,
                         cudaFuncAttributeMaxDynamicSharedMemorySize, SMEM_SCANC);

    k_wt<<<dim3(32, 8), dim3(32, 8)>>>(inproj);
    k_wc<<<512, 128>>>(mow, outp_w);
    k_ln<<<256, 256>>>(input, input2, ln_g, ln_b);
    k_mma<256, false><<<dim3(128, 8), 256, SMEM_MMA>>>(wtH, wtL, xnH, xnL, nullptr, nullptr);
    k_conv<<<dim3(16, 512), 256>>>(conv_w, conv_b);
    k_xproj<<<256, 256>>>(xproj, dtw, dtb);
    k_scanA<<<dim3(32, 64), 256>>>(A_log);
    k_scanB<<<128, 256>>>();
    k_scanC<<<dim3(32, 64), 256, SMEM_SCANC>>>(A_log, Dp);
    k_mma<512, true><<<dim3(128, 1), 256, SMEM_MMA>>>(wcH, wcL, yH, yL, out, outp_b);
}

// round 17
// speedup vs baseline: 1.1055x; 1.0545x over previous
#include <cuda_runtime.h>
#include <cuda_bf16.h>
#include <cstdint>

typedef unsigned long long ull;

#define M_TOT 16384   // B * L
#define L_SEQ 4096
#define NCHUNK 64
#define CLEN 64
#define LOG2E 1.4426950408889634f
#define SPITCH 68     // scan smem row pitch (floats): 16B-aligned, conflict-free

// ---------------- scratch ----------------------------------------------------
__device__ __align__(16) float g_xz[512 * M_TOT];     // in_proj x-branch, fp32 (conv input)
__device__ __align__(16) float g_xdbl[M_TOT * 48];    // x_proj out, (m, j)
__device__ __align__(16) float g_delta[512 * M_TOT];  // softplus, (d, m)
__device__ __align__(16) float g_P[NCHUNK * 2048 * 16];
__device__ __align__(16) float g_Lh[NCHUNK * 2048 * 16];
__device__ __align__(16) float g_H[NCHUNK * 2048 * 16];
__device__ __align__(16) __nv_bfloat16 g_xsH[512 * M_TOT];  // conv+silu hi, (d,m)
__device__ __align__(16) __nv_bfloat16 g_xsL[512 * M_TOT];  // conv+silu lo
__device__ __align__(16) __nv_bfloat16 g_zsH[512 * M_TOT];  // silu(z) hi, (d,m)
__device__ __align__(16) __nv_bfloat16 g_zsL[512 * M_TOT];  // silu(z) lo
__device__ __align__(16) __nv_bfloat16 g_XnH[256 * M_TOT];
__device__ __align__(16) __nv_bfloat16 g_XnL[256 * M_TOT];
__device__ __align__(16) __nv_bfloat16 g_yH[512 * M_TOT];
__device__ __align__(16) __nv_bfloat16 g_yL[512 * M_TOT];
__device__ __align__(16) __nv_bfloat16 g_WtH[1024 * 256];
__device__ __align__(16) __nv_bfloat16 g_WtL[1024 * 256];
__device__ __align__(16) __nv_bfloat16 g_WcH[128 * 512];
__device__ __align__(16) __nv_bfloat16 g_WcL[128 * 512];

// ---------------- helpers ----------------------------------------------------
__device__ __forceinline__ uint32_t smem_u32(const void* p) {
    uint32_t a;
    asm("{ .reg .u64 t; cvta.to.shared.u64 t, %1; cvt.u32.u64 %0, t; }" : "=r"(a) : "l"(p));
    return a;
}
__device__ __forceinline__ float ex2(float x) {
    float r;
    asm("ex2.approx.f32 %0, %1;" : "=f"(r) : "f"(x));
    return r;
}
__device__ __forceinline__ void ldsm4(uint32_t* r, uint32_t addr) {
    asm volatile("ldmatrix.sync.aligned.m8n8.x4.shared.b16 {%0,%1,%2,%3}, [%4];"
        : "=r"(r[0]), "=r"(r[1]), "=r"(r[2]), "=r"(r[3]) : "r"(addr));
}
__device__ __forceinline__ void ldsm4t(uint32_t* r, uint32_t addr) {
    asm volatile("ldmatrix.sync.aligned.m8n8.x4.trans.shared.b16 {%0,%1,%2,%3}, [%4];"
        : "=r"(r[0]), "=r"(r[1]), "=r"(r[2]), "=r"(r[3]) : "r"(addr));
}
__device__ __forceinline__ void mma_bf16(float* d, const uint32_t* a, const uint32_t* b) {
    asm volatile("mma.sync.aligned.m16n8k16.row.col.f32.bf16.bf16.f32 "
        "{%0,%1,%2,%3}, {%4,%5,%6,%7}, {%8,%9}, {%0,%1,%2,%3};"
        : "+f"(d[0]), "+f"(d[1]), "+f"(d[2]), "+f"(d[3])
        : "r"(a[0]), "r"(a[1]), "r"(a[2]), "r"(a[3]), "r"(b[0]), "r"(b[1]));
}
// load 4 floats reconstructed from bf16 hi/lo arrays (idx 4-elem aligned)
__device__ __forceinline__ float4 ld_hl4(const __nv_bfloat16* __restrict__ H,
                                         const __nv_bfloat16* __restrict__ L, size_t idx) {
    uint2 uh = *(const uint2*)(H + idx);
    uint2 ul = *(const uint2*)(L + idx);
    __nv_bfloat162 a, b, c, d;
    *(uint32_t*)&a = uh.x; *(uint32_t*)&b = uh.y;
    *(uint32_t*)&c = ul.x; *(uint32_t*)&d = ul.y;
    float2 fa = __bfloat1622float2(a), fb = __bfloat1622float2(b);
    float2 fc = __bfloat1622float2(c), fd = __bfloat1622float2(d);
    return make_float4(fa.x + fc.x, fa.y + fc.y, fb.x + fd.x, fb.y + fd.y);
}
// store 2 floats split hi/lo (idx 2-elem aligned)
__device__ __forceinline__ void st_hl2(__nv_bfloat16* __restrict__ H,
                                       __nv_bfloat16* __restrict__ L,
                                       size_t idx, float2 v) {
    __nv_bfloat16 h0 = __float2bfloat16(v.x), h1 = __float2bfloat16(v.y);
    __nv_bfloat16 l0 = __float2bfloat16(v.x - __bfloat162float(h0));
    __nv_bfloat16 l1 = __float2bfloat16(v.y - __bfloat162float(h1));
    __nv_bfloat162 hh; hh.x = h0; hh.y = h1;
    __nv_bfloat162 ll; ll.x = l0; ll.y = l1;
    *(__nv_bfloat162*)(H + idx) = hh;
    *(__nv_bfloat162*)(L + idx) = ll;
}
#define CPA16(dst, src) asm volatile("cp.async.cg.shared.global [%0], [%1], 16;" :: "r"(dst), "l"(src))
#define CPA_COMMIT()    asm volatile("cp.async.commit_group;" ::: "memory")
#define CPA_WAIT(n)     asm volatile("cp.async.wait_group %0;" :: "n"(n) : "memory")

// ---------------- K_wt: split-transpose in_proj_w -> [n][k] bf16 ------------
__global__ void k_wt(const float* __restrict__ W) {
    __shared__ float t[32][33];
    int n0 = blockIdx.x * 32, k0 = blockIdx.y * 32;
    int x = threadIdx.x, y0 = threadIdx.y;
    for (int yy = y0; yy < 32; yy += 8) t[yy][x] = W[(k0 + yy) * 1024 + n0 + x];
    __syncthreads();
    for (int yy = y0; yy < 32; yy += 8) {
        float v = t[x][yy];
        __nv_bfloat16 h = __float2bfloat16(v);
        __nv_bfloat16 l = __float2bfloat16(v - __bfloat162float(h));
        g_WtH[(size_t)(n0 + yy) * 256 + k0 + x] = h;
        g_WtL[(size_t)(n0 + yy) * 256 + k0 + x] = l;
    }
}

// ---------------- K_wc: (mow @ outp_w)^T split ------------------------------
__global__ void k_wc(const float* __restrict__ mw, const float* __restrict__ ow) {
    int d = blockIdx.x, e = threadIdx.x;
    float acc = 0.f;
#pragma unroll 8
    for (int c = 0; c < 256; ++c)
        acc = fmaf(mw[d * 256 + c], ow[c * 128 + e], acc);
    __nv_bfloat16 h = __float2bfloat16(acc);
    __nv_bfloat16 l = __float2bfloat16(acc - __bfloat162float(h));
    g_WcH[(size_t)e * 512 + d] = h;
    g_WcL[(size_t)e * 512 + d] = l;
}

// ---------------- K1: concat + LN, 4 threads per token ----------------------
__global__ void __launch_bounds__(256) k_ln(const float* __restrict__ in1,
                                            const float* __restrict__ in2,
                                            const float* __restrict__ gg,
                                            const float* __restrict__ bb) {
    __shared__ float sg[256], sb[256];
    __shared__ float red[2][4][64];
    int tid = threadIdx.x;
    int q = tid >> 6, ml = tid & 63;
    sg[tid] = gg[tid]; sb[tid] = bb[tid];

    int m = blockIdx.x * 64 + ml;
    int b = m >> 12, t = m & 4095;
    const float* src = ((q < 2) ? in1 : in2) + (size_t)b * 128 * 4096 + t;
    int c0 = (q & 1) * 64;

    float vals[64];
    float s = 0.f, s2 = 0.f;
#pragma unroll
    for (int i = 0; i < 64; ++i) {
        float v = src[(size_t)(c0 + i) * 4096];
        vals[i] = v; s += v; s2 += v * v;
    }
    red[0][q][ml] = s; red[1][q][ml] = s2;
    __syncthreads();
    s  = red[0][0][ml] + red[0][1][ml] + red[0][2][ml] + red[0][3][ml];
    s2 = red[1][0][ml] + red[1][1][ml] + red[1][2][ml] + red[1][3][ml];
    float mu = s * (1.f / 256.f);
    float var = s2 * (1.f / 256.f) - mu * mu;
    float rs = rsqrtf(var + 1e-5f);

    int cbase = q * 64;
#pragma unroll
    for (int i = 0; i < 64; ++i) {
        int c = cbase + i;
        float o = (vals[i] - mu) * rs * sg[c] + sb[c];
        __nv_bfloat16 h = __float2bfloat16(o);
        __nv_bfloat16 l = __float2bfloat16(o - __bfloat162float(h));
        g_XnH[(size_t)c * M_TOT + m] = h;
        g_XnL[(size_t)c * M_TOT + m] = l;
    }
}

// ---------------- warp-MMA GEMM: split bf16, KCH=32, 3-stage, 2 CTA/SM ------
// Stage: A_H[128 rows x 32k, pitch 80B] +A_L, B_H[32k x 128m, pitch 256B] +B_L.
// A: plain layout (pitch 80B = 20 words permutes banks; conflict-free ldsm).
// in_proj epilogue: n<512 -> fp32 g_xz; n>=512 -> silu(z) bf16 H/L.
#define STG_SZ 36864
#define SMEM_MMA 110592

template<int KT, bool IS_OUT>
__global__ void __launch_bounds__(256, 2) k_mma(
    const __nv_bfloat16* __restrict__ AH, const __nv_bfloat16* __restrict__ AL,
    const __nv_bfloat16* __restrict__ BH, const __nv_bfloat16* __restrict__ BL,
    float* __restrict__ outp, const float* __restrict__ bias)
{
    extern __shared__ __align__(16) char sm[];
    const int tid = threadIdx.x;
    const int lane = tid & 31, wid = tid >> 5;
    const int wr = wid & 1, wc = wid >> 1;
    const int m0 = blockIdx.x * 128, n0 = blockIdx.y * 128;
    const uint32_t smb = smem_u32(sm);
    const int NK = KT / 32;

    float acc[4][4][4];
#pragma unroll
    for (int i = 0; i < 4; ++i)
#pragma unroll
        for (int j = 0; j < 4; ++j)
#pragma unroll
            for (int p = 0; p < 4; ++p) acc[i][j][p] = 0.f;

    auto stage = [&](int kc, int stg) {
        uint32_t base = smb + stg * STG_SZ;
#pragma unroll
        for (int it = 0; it < 2; ++it) {
            int cid = it * 256 + tid;          // 0..511
            int row = cid >> 2, seg = cid & 3;
            size_t gof = (size_t)(n0 + row) * KT + kc * 32 + seg * 8;
            uint32_t off = row * 80 + seg * 16;
            CPA16(base + off, AH + gof);
            CPA16(base + 10240 + off, AL + gof);
        }
#pragma unroll
        for (int it = 0; it < 2; ++it) {
            int cid = it * 256 + tid;          // 0..511
            int k = cid >> 4, mseg = cid & 15;
            size_t gof = (size_t)(kc * 32 + k) * M_TOT + m0 + mseg * 8;
            uint32_t off = k * 256 + ((mseg ^ (k & 7)) << 4);
            CPA16(base + 20480 + off, BH + gof);
            CPA16(base + 28672 + off, BL + gof);
        }
    };

    stage(0, 0); CPA_COMMIT();
    if (NK > 1) { stage(1, 1); CPA_COMMIT(); }

    for (int kc = 0; kc < NK; ++kc) {
        if (kc + 1 < NK) CPA_WAIT(1); else CPA_WAIT(0);
        __syncthreads();
        if (kc + 2 < NK) { stage(kc + 2, (kc + 2) % 3); CPA_COMMIT(); }

        uint32_t sa_h = smb + (kc % 3) * STG_SZ;
        uint32_t sa_l = sa_h + 10240;
        uint32_t sb_h = sa_h + 20480;
        uint32_t sb_l = sa_h + 28672;

#pragma unroll
        for (int ks = 0; ks < 2; ++ks) {
            uint32_t afh[4][4], afl[4][4];
            {
                int row = wr * 64 + (lane & 7) + ((lane >> 3) & 1) * 8;
                int seg = ks * 2 + (lane >> 4);
#pragma unroll
                for (int rt = 0; rt < 4; ++rt) {
                    int r = row + rt * 16;
                    uint32_t off = r * 80 + seg * 16;
                    ldsm4(afh[rt], sa_h + off);
                    ldsm4(afl[rt], sa_l + off);
                }
            }
            uint32_t bfh[4][2], bfl[4][2];
            {
                int k = ks * 16 + (lane & 7) + ((lane >> 3) & 1) * 8;
#pragma unroll
                for (int half = 0; half < 2; ++half) {
                    int mseg = wc * 4 + half * 2 + (lane >> 4);
                    uint32_t off = k * 256 + ((mseg ^ (k & 7)) << 4);
                    uint32_t r[4];
                    ldsm4t(r, sb_h + off);
                    bfh[half * 2][0] = r[0]; bfh[half * 2][1] = r[1];
                    bfh[half * 2 + 1][0] = r[2]; bfh[half * 2 + 1][1] = r[3];
                    ldsm4t(r, sb_l + off);
                    bfl[half * 2][0] = r[0]; bfl[half * 2][1] = r[1];
                    bfl[half * 2 + 1][0] = r[2]; bfl[half * 2 + 1][1] = r[3];
                }
            }
#pragma unroll
            for (int rt = 0; rt < 4; ++rt)
#pragma unroll
                for (int ct = 0; ct < 4; ++ct) {
                    mma_bf16(acc[rt][ct], afh[rt], bfh[ct]);
                    mma_bf16(acc[rt][ct], afh[rt], bfl[ct]);
                    mma_bf16(acc[rt][ct], afl[rt], bfh[ct]);
                }
        }
    }

    const bool ZPART = (!IS_OUT) && (n0 >= 512);
#pragma unroll
    for (int rt = 0; rt < 4; ++rt) {
        int row0 = n0 + wr * 64 + rt * 16 + (lane >> 2);
        int row1 = row0 + 8;
        float b0 = 0.f, b1 = 0.f;
        if (IS_OUT) { b0 = bias[row0]; b1 = bias[row1]; }
#pragma unroll
        for (int ct = 0; ct < 4; ++ct) {
            int col = m0 + wc * 32 + ct * 8 + (lane & 3) * 2;
            float2 v0 = make_float2(acc[rt][ct][0] + b0, acc[rt][ct][1] + b0);
            float2 v1 = make_float2(acc[rt][ct][2] + b1, acc[rt][ct][3] + b1);
            if (IS_OUT) {
                int bb = col >> 12, t = col & 4095;
                *(float2*)&outp[((size_t)(bb * 128 + row0) << 12) + t] = v0;
                *(float2*)&outp[((size_t)(bb * 128 + row1) << 12) + t] = v1;
            } else if (ZPART) {
                float2 s0 = make_float2(v0.x / (1.f + __expf(-v0.x)),
                                        v0.y / (1.f + __expf(-v0.y)));
                float2 s1 = make_float2(v1.x / (1.f + __expf(-v1.x)),
                                        v1.y / (1.f + __expf(-v1.y)));
                st_hl2(g_zsH, g_zsL, (size_t)(row0 - 512) * M_TOT + col, s0);
                st_hl2(g_zsH, g_zsL, (size_t)(row1 - 512) * M_TOT + col, s1);
            } else {
                *(float2*)&outp[(size_t)row0 * M_TOT + col] = v0;
                *(float2*)&outp[(size_t)row1 * M_TOT + col] = v1;
            }
        }
    }
}

// ---------------- K3: causal dwconv(4) + bias + silu -> bf16 H/L ------------
__global__ void k_conv(const float* __restrict__ cw, const float* __restrict__ cb) {
    int d = blockIdx.y;
    int m4 = (blockIdx.x * 256 + threadIdx.x) * 4;
    int t4 = m4 & 4095;
    const float* row = g_xz + (size_t)d * M_TOT;
    float4 v = *(const float4*)&row[m4];
    float4 vp = (t4 == 0) ? make_float4(0.f, 0.f, 0.f, 0.f)
                          : *(const float4*)&row[m4 - 4];
    float w0 = cw[d * 4 + 0], w1 = cw[d * 4 + 1], w2 = cw[d * 4 + 2], w3 = cw[d * 4 + 3];
    float bia = cb[d];
    float4 o;
    o.x = bia + w3 * v.x + w2 * vp.w + w1 * vp.z + w0 * vp.y;
    o.y = bia + w3 * v.y + w2 * v.x + w1 * vp.w + w0 * vp.z;
    o.z = bia + w3 * v.z + w2 * v.y + w1 * v.x + w0 * vp.w;
    o.w = bia + w3 * v.w + w2 * v.z + w1 * v.y + w0 * v.x;
    o.x = o.x / (1.f + __expf(-o.x));
    o.y = o.y / (1.f + __expf(-o.y));
    o.z = o.z / (1.f + __expf(-o.z));
    o.w = o.w / (1.f + __expf(-o.w));
    size_t idx = (size_t)d * M_TOT + m4;
    st_hl2(g_xsH, g_xsL, idx, make_float2(o.x, o.y));
    st_hl2(g_xsH, g_xsL, idx + 2, make_float2(o.z, o.w));
}

// ---------------- K4: x_proj + dt_proj fused, m-tile 64, grid 256 -----------
__global__ void __launch_bounds__(256) k_xproj(const float* __restrict__ xw,
                                               const float* __restrict__ dtw,
                                               const float* __restrict__ db) {
    __shared__ __align__(16) float Ash[32][64];
    __shared__ float Wsh[32][48];
    __shared__ float sdt[64][17];
    __shared__ float shw[16][128];
    __shared__ float shb[128];
    int tid = threadIdx.x;
    int m0 = blockIdx.x * 64;
    int tj = tid >> 5, tm = tid & 31;
    float acc[6][2] = {};

    for (int k0 = 0; k0 < 512; k0 += 32) {
#pragma unroll
        for (int r = 0; r < 2; ++r) {
            int lin = r * 256 + tid;
            int row = lin >> 4, c4 = (lin & 15) << 2;
            float4 f = ld_hl4(g_xsH, g_xsL, (size_t)(k0 + row) * M_TOT + m0 + c4);
            *(float4*)&Ash[row][c4] = f;
        }
#pragma unroll
        for (int r = 0; r < 6; ++r) {
            int lin = r * 256 + tid;
            int row = lin / 48, col = lin % 48;
            Wsh[row][col] = xw[(k0 + row) * 48 + col];
        }
        __syncthreads();
#pragma unroll
        for (int kk = 0; kk < 32; ++kk) {
            float2 a = *(const float2*)&Ash[kk][tm * 2];
#pragma unroll
            for (int q = 0; q < 6; ++q) {
                float w = Wsh[kk][tj * 6 + q];
                acc[q][0] = fmaf(w, a.x, acc[q][0]);
                acc[q][1] = fmaf(w, a.y, acc[q][1]);
            }
        }
        __syncthreads();
    }
#pragma unroll
    for (int p = 0; p < 2; ++p) {
        int mloc = tm * 2 + p;
#pragma unroll
        for (int q = 0; q < 6; ++q) {
            int j = tj * 6 + q;
            if (j < 16) sdt[mloc][j] = acc[q][p];
            else g_xdbl[(size_t)(m0 + mloc) * 48 + j] = acc[q][p];
        }
    }
    __syncthreads();

    int mloc = tid & 63, dseg = tid >> 6;
    float rr[16];
#pragma unroll
    for (int r = 0; r < 16; ++r) rr[r] = sdt[mloc][r];

    for (int dq = 0; dq < 4; ++dq) {
#pragma unroll
        for (int r = 0; r < 8; ++r) {
            int lin = r * 256 + tid;
            int row = lin >> 7, col = lin & 127;
            shw[row][col] = dtw[row * 512 + dq * 128 + col];
        }
        if (tid < 128) shb[tid] = db[dq * 128 + tid];
        __syncthreads();
#pragma unroll 4
        for (int dd = 0; dd < 32; ++dd) {
            int dcol = dseg * 32 + dd;
            float a = shb[dcol];
#pragma unroll
            for (int r = 0; r < 16; ++r) a = fmaf(rr[r], shw[r][dcol], a);
            float sp = (a > 20.f) ? a : log1pf(__expf(a));
            g_delta[(size_t)(dq * 128 + dcol) * M_TOT + m0 + mloc] = sp;
        }
        __syncthreads();
    }
}

// ---------------- chunked scan, smem-staged ----------------------------------
__global__ void __launch_bounds__(256) k_scanA(const float* __restrict__ A_log) {
    __shared__ __align__(16) float sdl[64 * SPITCH];
    __shared__ __align__(16) float sx[64 * SPITCH];
    __shared__ __align__(16) float sB[64 * 16];
    int tid = threadIdx.x;
    int l = tid & 3, g = tid >> 2;
    int p0 = blockIdx.x * 64;
    int b = p0 >> 9, d0 = p0 & 511;
    int c = blockIdx.y;
    size_t rowbase = (size_t)b * L_SEQ + c * CLEN;

#pragma unroll
    for (int it = 0; it < 4; ++it) {
        int lin = it * 256 + tid;
        int row = lin >> 4, tq = (lin & 15) << 2;
        size_t gofs = (size_t)(d0 + row) * M_TOT + rowbase + tq;
        *(float4*)&sdl[row * SPITCH + tq] = *(const float4*)&g_delta[gofs];
        *(float4*)&sx[row * SPITCH + tq]  = ld_hl4(g_xsH, g_xsL, gofs);
    }
    {
        int t = tid >> 2, n4 = (tid & 3) << 2;
        *(float4*)&sB[t * 16 + n4] = *(const float4*)&g_xdbl[(rowbase + t) * 48 + 16 + n4];
    }
    int d = d0 + g;
    float A0 = -__expf(A_log[d * 16 + 4 * l + 0]) * LOG2E;
    float A1 = -__expf(A_log[d * 16 + 4 * l + 1]) * LOG2E;
    float A2 = -__expf(A_log[d * 16 + 4 * l + 2]) * LOG2E;
    float A3 = -__expf(A_log[d * 16 + 4 * l + 3]) * LOG2E;
    __syncthreads();

    float h0 = 0.f, h1 = 0.f, h2 = 0.f, h3 = 0.f, S = 0.f;
#pragma unroll 4
    for (int t = 0; t < CLEN; ++t) {
        float dl = sdl[g * SPITCH + t];
        float xv = sx[g * SPITCH + t];
        float4 Bv = *(const float4*)&sB[t * 16 + 4 * l];
        float e0 = ex2(dl * A0), e1 = ex2(dl * A1);
        float e2 = ex2(dl * A2), e3 = ex2(dl * A3);
        float du = dl * xv;
        h0 = fmaf(h0, e0, du * Bv.x);
        h1 = fmaf(h1, e1, du * Bv.y);
        h2 = fmaf(h2, e2, du * Bv.z);
        h3 = fmaf(h3, e3, du * Bv.w);
        S += dl;
    }
    int idx = c * 32768 + (p0 + g) * 16 + 4 * l;
    *(float4*)&g_P[idx]  = make_float4(ex2(A0 * S), ex2(A1 * S), ex2(A2 * S), ex2(A3 * S));
    *(float4*)&g_Lh[idx] = make_float4(h0, h1, h2, h3);
}

// Phase B: scan across chunks.
__global__ void __launch_bounds__(256) k_scanB() {
    int gid = blockIdx.x * 256 + threadIdx.x;
    float h = 0.f;
#pragma unroll 8
    for (int c = 0; c < NCHUNK; ++c) {
        int idx = c * 32768 + gid;
        g_H[idx] = h;
        h = fmaf(h, g_P[idx], g_Lh[idx]);
    }
}

// Phase C: recompute + gate (pre-siluted z) + coalesced bf16 y store.
#define SMEM_SCANC ((4 * 64 * SPITCH + 2 * 64 * 16) * 4)
__global__ void __launch_bounds__(256) k_scanC(const float* __restrict__ A_log,
                                               const float* __restrict__ Dp_) {
    extern __shared__ __align__(16) float smc[];
    float* sdl = smc;                        // [64][SPITCH]
    float* sx  = sdl + 64 * SPITCH;
    float* sz  = sx  + 64 * SPITCH;          // silu(z), reconstructed fp32
    float* sy  = sz  + 64 * SPITCH;          // [64][SPITCH]
    float* sB  = sy  + 64 * SPITCH;          // [64*16]
    float* sC  = sB  + 64 * 16;

    int tid = threadIdx.x;
    int l = tid & 3, g = tid >> 2;
    int p0 = blockIdx.x * 64;
    int b = p0 >> 9, d0 = p0 & 511;
    int c = blockIdx.y;
    size_t rowbase = (size_t)b * L_SEQ + c * CLEN;

#pragma unroll
    for (int it = 0; it < 4; ++it) {
        int lin = it * 256 + tid;
        int row = lin >> 4, tq = (lin & 15) << 2;
        size_t gofs = (size_t)(d0 + row) * M_TOT + rowbase + tq;
        *(float4*)&sdl[row * SPITCH + tq] = *(const float4*)&g_delta[gofs];
        *(float4*)&sx[row * SPITCH + tq]  = ld_hl4(g_xsH, g_xsL, gofs);
        *(float4*)&sz[row * SPITCH + tq]  = ld_hl4(g_zsH, g_zsL, gofs);
    }
    {
        int t = tid >> 2, n4 = (tid & 3) << 2;
        *(float4*)&sB[t * 16 + n4] = *(const float4*)&g_xdbl[(rowbase + t) * 48 + 16 + n4];
        *(float4*)&sC[t * 16 + n4] = *(const float4*)&g_xdbl[(rowbase + t) * 48 + 32 + n4];
    }
    int d = d0 + g;
    float A0 = -__expf(A_log[d * 16 + 4 * l + 0]) * LOG2E;
    float A1 = -__expf(A_log[d * 16 + 4 * l + 1]) * LOG2E;
    float A2 = -__expf(A_log[d * 16 + 4 * l + 2]) * LOG2E;
    float A3 = -__expf(A_log[d * 16 + 4 * l + 3]) * LOG2E;
    float Dv = Dp_[d];
    __syncthreads();

    int idx = c * 32768 + (p0 + g) * 16 + 4 * l;
    float4 hh = *(const float4*)&g_H[idx];
    float h0 = hh.x, h1 = hh.y, h2 = hh.z, h3 = hh.w;

#pragma unroll 4
    for (int t = 0; t < CLEN; ++t) {
        float dl = sdl[g * SPITCH + t];
        float xv = sx[g * SPITCH + t];
        float4 Bv = *(const float4*)&sB[t * 16 + 4 * l];
        float4 Cv = *(const float4*)&sC[t * 16 + 4 * l];
        float e0 = ex2(dl * A0), e1 = ex2(dl * A1);
        float e2 = ex2(dl * A2), e3 = ex2(dl * A3);
        float du = dl * xv;
        h0 = fmaf(h0, e0, du * Bv.x);
        h1 = fmaf(h1, e1, du * Bv.y);
        h2 = fmaf(h2, e2, du * Bv.z);
        h3 = fmaf(h3, e3, du * Bv.w);
        float pr = h0 * Cv.x;
        pr = fmaf(h1, Cv.y, pr);
        pr = fmaf(h2, Cv.z, pr);
        pr = fmaf(h3, Cv.w, pr);
        pr += __shfl_xor_sync(0xffffffffu, pr, 1);
        pr += __shfl_xor_sync(0xffffffffu, pr, 2);
        if (l == 0) {
            float yv = fmaf(xv, Dv, pr);
            sy[g * SPITCH + t] = yv * sz[g * SPITCH + t];   // z already silu'd
        }
    }
    __syncthreads();

#pragma unroll
    for (int i = 0; i < 16; ++i) {
        int elem = i * 256 + tid;
        int row = elem >> 6, t = elem & 63;
        float yv = sy[row * SPITCH + t];
        __nv_bfloat16 yh = __float2bfloat16(yv);
        __nv_bfloat16 yl = __float2bfloat16(yv - __bfloat162float(yh));
        size_t gof = (size_t)(d0 + row) * M_TOT + rowbase + t;
        g_yH[gof] = yh;
        g_yL[gof] = yl;
    }
}

// ---------------- launch -----------------------------------------------------
extern "C" void kernel_launch(void* const* d_in, const int* in_sizes, int n_in,
                              void* d_out, int out_size) {
    const float* input  = (const float*)d_in[0];
    const float* input2 = (const float*)d_in[1];
    const float* ln_g   = (const float*)d_in[2];
    const float* ln_b   = (const float*)d_in[3];
    const float* outp_w = (const float*)d_in[4];
    const float* outp_b = (const float*)d_in[5];
    const float* inproj = (const float*)d_in[6];
    const float* conv_w = (const float*)d_in[7];
    const float* conv_b = (const float*)d_in[8];
    const float* xproj  = (const float*)d_in[9];
    const float* dtw    = (const float*)d_in[10];
    const float* dtb    = (const float*)d_in[11];
    const float* A_log  = (const float*)d_in[12];
    const float* Dp     = (const float*)d_in[13];
    const float* mow    = (const float*)d_in[14];
    float* out = (float*)d_out;

    __nv_bfloat16 *wtH, *wtL, *wcH, *wcL, *xnH, *xnL, *yH, *yL;
    float *xz;
    cudaGetSymbolAddress((void**)&wtH, g_WtH);
    cudaGetSymbolAddress((void**)&wtL, g_WtL);
    cudaGetSymbolAddress((void**)&wcH, g_WcH);
    cudaGetSymbolAddress((void**)&wcL, g_WcL);
    cudaGetSymbolAddress((void**)&xnH, g_XnH);
    cudaGetSymbolAddress((void**)&xnL, g_XnL);
    cudaGetSymbolAddress((void**)&yH, g_yH);
    cudaGetSymbolAddress((void**)&yL, g_yL);
    cudaGetSymbolAddress((void**)&xz, g_xz);

    cudaFuncSetAttribute(k_mma<256, false>,
                         cudaFuncAttributeMaxDynamicSharedMemorySize, SMEM_MMA);
    cudaFuncSetAttribute(k_mma<512, true>,
                         cudaFuncAttributeMaxDynamicSharedMemorySize, SMEM_MMA);
    cudaFuncSetAttribute(k_scanC,
                         cudaFuncAttributeMaxDynamicSharedMemorySize, SMEM_SCANC);

    k_wt<<<dim3(32, 8), dim3(32, 8)>>>(inproj);
    k_wc<<<512, 128>>>(mow, outp_w);
    k_ln<<<256, 256>>>(input, input2, ln_g, ln_b);
    k_mma<256, false><<<dim3(128, 8), 256, SMEM_MMA>>>(wtH, wtL, xnH, xnL, xz, nullptr);
    k_conv<<<dim3(16, 512), 256>>>(conv_w, conv_b);
    k_xproj<<<256, 256>>>(xproj, dtw, dtb);
    k_scanA<<<dim3(32, 64), 256>>>(A_log);
    k_scanB<<<128, 256>>>();
    k_scanC<<<dim3(32, 64), 256, SMEM_SCANC>>>(A_log, Dp);
    k_mma<512, true><<<dim3(128, 1), 256, SMEM_MMA>>>(wcH, wcL, yH, yL, out, outp_b);
}